// round 1
// baseline (speedup 1.0000x reference)
#include <cuda_runtime.h>
#include <cstdint>
#include <cstddef>

// ---------------------------------------------------------------------------
// Problem constants: B=16, L=4096, D=H=512
// ---------------------------------------------------------------------------
constexpr int Bb   = 16;
constexpr int Lseq = 4096;
constexpr int Dm   = 512;
constexpr int Hh   = 512;
constexpr int MROWS = Bb * Lseq;          // 65536
constexpr int DFF  = 2048;                // 4*D

// ---------------------------------------------------------------------------
// Scratch (device globals: allocation-free per harness rules)
// ---------------------------------------------------------------------------
__device__ float g_Z [(size_t)MROWS * Hh];   // z projection
__device__ float g_F [(size_t)MROWS * Hh];   // sigmoid(forget)
__device__ float g_R [(size_t)MROWS * Hh];   // sigmoid(reset)
__device__ float g_HW[(size_t)MROWS * Dm];   // post-SRU+highway (pre-LN1)
__device__ float g_X1[(size_t)MROWS * Dm];   // post-LN1
__device__ float g_H4[(size_t)MROWS * DFF];  // gelu(x1@W1+b1)
__device__ float g_X2[(size_t)MROWS * Dm];   // pre-LN2

// ---------------------------------------------------------------------------
// Small helpers
// ---------------------------------------------------------------------------
__device__ __forceinline__ uint32_t f2tf32(float x) {
    uint32_t r;
    asm("cvt.rna.tf32.f32 %0, %1;" : "=r"(r) : "f"(x));
    return r;
}

__device__ __forceinline__ void cp16(void* dst, const void* src) {
    unsigned d = (unsigned)__cvta_generic_to_shared(dst);
    asm volatile("cp.async.cg.shared.global [%0], [%1], 16;\n" :: "r"(d), "l"(src));
}
__device__ __forceinline__ void cp_commit() { asm volatile("cp.async.commit_group;\n"); }
__device__ __forceinline__ void cp_wait0()  { asm volatile("cp.async.wait_group 0;\n"); }

__device__ __forceinline__ void mma8(float* c, const uint32_t* a, const uint32_t* b) {
    asm volatile(
        "mma.sync.aligned.m16n8k8.row.col.f32.tf32.tf32.f32 "
        "{%0,%1,%2,%3},{%4,%5,%6,%7},{%8,%9},{%0,%1,%2,%3};\n"
        : "+f"(c[0]), "+f"(c[1]), "+f"(c[2]), "+f"(c[3])
        : "r"(a[0]), "r"(a[1]), "r"(a[2]), "r"(a[3]), "r"(b[0]), "r"(b[1]));
}

__device__ __forceinline__ float sigmoidf_(float v) { return 1.0f / (1.0f + expf(-v)); }
__device__ __forceinline__ float gelu_(float v) {
    return 0.5f * v * (1.0f + erff(v * 0.70710678118654752440f));
}

// ---------------------------------------------------------------------------
// tf32 GEMM: C[M,N] = A[M,K] @ W[K,N], fused epilogues.
//   EPI=0: SRU projection  -> g_Z | g_F=sigmoid(+b_f) | g_R=sigmoid(+b_r)
//   EPI=1: MLP up          -> g_H4 = gelu(v + b1)   (A = g_X1)
//   EPI=2: MLP down + res  -> g_X2 = v + b2 + g_X1  (A = g_H4)
// Block tile 128x128x16, 256 threads (2x4 warps, each 64x32), double-buffered
// cp.async, padded smem (conflict-free fragment loads).
// ---------------------------------------------------------------------------
constexpr int BM = 128, BN = 128, BK = 16;
constexpr int ASTR = BK + 4;   // 20 (keeps 16B alignment, kills bank conflicts)
constexpr int BSTR = BN + 4;   // 132

template<int EPI, int N, int K>
__global__ __launch_bounds__(256, 2) void gemm_tf32(
    const float* __restrict__ Aparam,
    const float* __restrict__ W,
    const float* __restrict__ bias,
    const float* __restrict__ bias2)
{
    const float* __restrict__ A =
        (EPI == 0) ? Aparam : ((EPI == 1) ? (const float*)g_X1 : (const float*)g_H4);

    __shared__ float As[2][BM * ASTR];
    __shared__ float Bs[2][BK * BSTR];

    const int t    = threadIdx.x;
    const int m0   = blockIdx.y * BM;
    const int n0   = blockIdx.x * BN;
    const int lane = t & 31, wid = t >> 5;
    const int gq   = lane >> 2, tg = lane & 3;
    const int wm   = (wid >> 2) * 64;   // warp m offset (2 rows of warps)
    const int wn   = (wid & 3) * 32;    // warp n offset (4 cols of warps)

    float acc[4][4][4];
    #pragma unroll
    for (int i = 0; i < 4; i++)
        #pragma unroll
        for (int j = 0; j < 4; j++)
            #pragma unroll
            for (int r = 0; r < 4; r++) acc[i][j][r] = 0.0f;

    auto load_tiles = [&](int kt, int s) {
        #pragma unroll
        for (int i = 0; i < 2; i++) {              // A: 128x16 floats, 512 x 16B chunks
            int idx = t + i * 256;
            int row = idx >> 2, c4 = (idx & 3) << 2;
            cp16(&As[s][row * ASTR + c4],
                 A + (size_t)(m0 + row) * K + (size_t)kt * BK + c4);
        }
        #pragma unroll
        for (int i = 0; i < 2; i++) {              // B: 16x128 floats
            int idx = t + i * 256;
            int row = idx >> 5, c4 = (idx & 31) << 2;
            cp16(&Bs[s][row * BSTR + c4],
                 W + (size_t)(kt * BK + row) * N + n0 + c4);
        }
        cp_commit();
    };

    load_tiles(0, 0);
    const int KT = K / BK;

    for (int kt = 0; kt < KT; ++kt) {
        cp_wait0();
        __syncthreads();
        if (kt + 1 < KT) load_tiles(kt + 1, (kt + 1) & 1);

        const float* as = As[kt & 1];
        const float* bs = Bs[kt & 1];

        #pragma unroll
        for (int kk = 0; kk < BK; kk += 8) {
            uint32_t af[4][4], bf[4][2];
            #pragma unroll
            for (int mi = 0; mi < 4; mi++) {
                int r0 = wm + mi * 16 + gq;
                af[mi][0] = f2tf32(as[(r0    ) * ASTR + kk + tg    ]);
                af[mi][1] = f2tf32(as[(r0 + 8) * ASTR + kk + tg    ]);
                af[mi][2] = f2tf32(as[(r0    ) * ASTR + kk + tg + 4]);
                af[mi][3] = f2tf32(as[(r0 + 8) * ASTR + kk + tg + 4]);
            }
            #pragma unroll
            for (int ni = 0; ni < 4; ni++) {
                int c0 = wn + ni * 8 + gq;
                bf[ni][0] = f2tf32(bs[(kk + tg    ) * BSTR + c0]);
                bf[ni][1] = f2tf32(bs[(kk + tg + 4) * BSTR + c0]);
            }
            #pragma unroll
            for (int mi = 0; mi < 4; mi++)
                #pragma unroll
                for (int ni = 0; ni < 4; ni++)
                    mma8(acc[mi][ni], af[mi], bf[ni]);
        }
    }

    // Epilogue
    #pragma unroll
    for (int mi = 0; mi < 4; mi++) {
        #pragma unroll
        for (int ni = 0; ni < 4; ni++) {
            #pragma unroll
            for (int half = 0; half < 2; half++) {
                int row = m0 + wm + mi * 16 + gq + half * 8;
                int col = n0 + wn + ni * 8 + tg * 2;
                float v0 = acc[mi][ni][half * 2 + 0];
                float v1 = acc[mi][ni][half * 2 + 1];
                size_t rw = (size_t)row;
                if (EPI == 0) {
                    if (col < Hh) {
                        g_Z[rw * Hh + col]     = v0;
                        g_Z[rw * Hh + col + 1] = v1;
                    } else if (col < 2 * Hh) {
                        int h = col - Hh;
                        g_F[rw * Hh + h]     = sigmoidf_(v0 + bias[h]);
                        g_F[rw * Hh + h + 1] = sigmoidf_(v1 + bias[h + 1]);
                    } else {
                        int h = col - 2 * Hh;
                        g_R[rw * Hh + h]     = sigmoidf_(v0 + bias2[h]);
                        g_R[rw * Hh + h + 1] = sigmoidf_(v1 + bias2[h + 1]);
                    }
                } else if (EPI == 1) {
                    g_H4[rw * N + col]     = gelu_(v0 + bias[col]);
                    g_H4[rw * N + col + 1] = gelu_(v1 + bias[col + 1]);
                } else {
                    g_X2[rw * N + col]     = v0 + bias[col]     + g_X1[rw * N + col];
                    g_X2[rw * N + col + 1] = v1 + bias[col + 1] + g_X1[rw * N + col + 1];
                }
            }
        }
    }
}

// ---------------------------------------------------------------------------
// SRU recurrence + highway, fused.  One thread per (b,h) chain; warp = 32
// consecutive h -> fully coalesced.  c_t = f*c + (1-f)*z ; hw = x + r*c + (1-r)*x
// ---------------------------------------------------------------------------
__global__ void sru_scan(const float* __restrict__ x)
{
    int t = blockIdx.x * blockDim.x + threadIdx.x;   // 0..8191
    int b = t >> 9;
    int h = t & (Hh - 1);
    size_t base = (size_t)b * Lseq * Hh + h;

    float c = 0.0f;
    #pragma unroll 4
    for (int l = 0; l < Lseq; ++l) {
        size_t i = base + (size_t)l * Hh;
        float f  = g_F[i];
        float z  = g_Z[i];
        float r  = g_R[i];
        float xv = x[i];
        c = fmaf(f, c - z, z);                    // f*c + (1-f)*z
        g_HW[i] = fmaf(r, c - xv, 2.0f * xv);     // 2x + r*(c - x)
    }
}

// ---------------------------------------------------------------------------
// LayerNorm over 512 elems: 1 block/row, 128 threads x float4.
//   WHICH=0: g_HW -> g_X1 ;  WHICH=1: g_X2 -> outp (d_out)
// ---------------------------------------------------------------------------
template<int WHICH>
__global__ void ln512(const float* __restrict__ gamma,
                      const float* __restrict__ beta,
                      float* __restrict__ outp)
{
    const float* in  = (WHICH == 0) ? (const float*)g_HW : (const float*)g_X2;
    float*       out = (WHICH == 0) ? (float*)g_X1 : outp;

    size_t row = blockIdx.x;
    int t = threadIdx.x;

    float4 v = ((const float4*)(in + row * Dm))[t];
    float s  = v.x + v.y + v.z + v.w;
    float sq = v.x*v.x + v.y*v.y + v.z*v.z + v.w*v.w;

    #pragma unroll
    for (int o = 16; o > 0; o >>= 1) {
        s  += __shfl_xor_sync(0xffffffffu, s,  o);
        sq += __shfl_xor_sync(0xffffffffu, sq, o);
    }
    __shared__ float ssum[4], ssq[4];
    int w = t >> 5;
    if ((t & 31) == 0) { ssum[w] = s; ssq[w] = sq; }
    __syncthreads();
    float S  = ssum[0] + ssum[1] + ssum[2] + ssum[3];
    float SQ = ssq[0] + ssq[1] + ssq[2] + ssq[3];

    float mean = S * (1.0f / 512.0f);
    float var  = SQ * (1.0f / 512.0f) - mean * mean;
    float rstd = rsqrtf(var + 1e-5f);

    float4 gg = ((const float4*)gamma)[t];
    float4 bb = ((const float4*)beta)[t];
    float4 o4;
    o4.x = (v.x - mean) * rstd * gg.x + bb.x;
    o4.y = (v.y - mean) * rstd * gg.y + bb.y;
    o4.z = (v.z - mean) * rstd * gg.z + bb.z;
    o4.w = (v.w - mean) * rstd * gg.w + bb.w;
    ((float4*)(out + row * Dm))[t] = o4;
}

// ---------------------------------------------------------------------------
// Launch
// ---------------------------------------------------------------------------
extern "C" void kernel_launch(void* const* d_in, const int* in_sizes, int n_in,
                              void* d_out, int out_size)
{
    const float* x    = (const float*)d_in[0];
    const float* Wsru = (const float*)d_in[1];
    const float* b_f  = (const float*)d_in[2];
    const float* b_r  = (const float*)d_in[3];
    const float* ln1g = (const float*)d_in[4];
    const float* ln1b = (const float*)d_in[5];
    const float* W1   = (const float*)d_in[6];
    const float* b1   = (const float*)d_in[7];
    const float* W2   = (const float*)d_in[8];
    const float* b2   = (const float*)d_in[9];
    const float* ln2g = (const float*)d_in[10];
    const float* ln2b = (const float*)d_in[11];
    float* out = (float*)d_out;

    // 1) u = x @ W_sru, fused gate sigmoids -> g_Z, g_F, g_R
    gemm_tf32<0, 3 * Hh, Dm><<<dim3((3 * Hh) / BN, MROWS / BM), 256>>>(x, Wsru, b_f, b_r);
    // 2) sequential recurrence + highway -> g_HW
    sru_scan<<<(Bb * Hh) / 64, 64>>>(x);
    // 3) LN1 -> g_X1
    ln512<0><<<MROWS, 128>>>(ln1g, ln1b, nullptr);
    // 4) h = gelu(x1 @ W1 + b1) -> g_H4
    gemm_tf32<1, DFF, Dm><<<dim3(DFF / BN, MROWS / BM), 256>>>(nullptr, W1, b1, nullptr);
    // 5) x2 = x1 + h @ W2 + b2 -> g_X2
    gemm_tf32<2, Dm, DFF><<<dim3(Dm / BN, MROWS / BM), 256>>>(nullptr, W2, b2, nullptr);
    // 6) LN2 -> d_out
    ln512<1><<<MROWS, 128>>>(ln2g, ln2b, out);
}

// round 2
// speedup vs baseline: 1.4812x; 1.4812x over previous
#include <cuda_runtime.h>
#include <cuda_fp16.h>
#include <cstdint>
#include <cstddef>

// ---------------------------------------------------------------------------
// Problem constants: B=16, L=4096, D=H=512
// ---------------------------------------------------------------------------
constexpr int Bb   = 16;
constexpr int Lseq = 4096;
constexpr int Dm   = 512;
constexpr int Hh   = 512;
constexpr int MROWS = Bb * Lseq;          // 65536
constexpr int DFF  = 2048;                // 4*D

// ---------------------------------------------------------------------------
// Scratch (device globals: allocation-free per harness rules)
// ---------------------------------------------------------------------------
__device__ __align__(16) __half g_Xh   [(size_t)MROWS * Dm];     // x in fp16 (GEMM1 A, scan)
__device__ __align__(16) __half g_Wsruh[(size_t)Dm * 3 * Hh];
__device__ __align__(16) __half g_W1h  [(size_t)Dm * DFF];
__device__ __align__(16) __half g_W2h  [(size_t)DFF * Dm];
__device__ __align__(16) __half g_Zh   [(size_t)MROWS * Hh];
__device__ __align__(16) __half g_Fh   [(size_t)MROWS * Hh];
__device__ __align__(16) __half g_Rh   [(size_t)MROWS * Hh];
__device__ __align__(16) float  g_HW   [(size_t)MROWS * Dm];     // pre-LN1 (fp32)
__device__ __align__(16) __half g_X1h  [(size_t)MROWS * Dm];     // post-LN1 (GEMM2 A + residual)
__device__ __align__(16) __half g_H4h  [(size_t)MROWS * DFF];    // gelu out (GEMM3 A)
__device__ __align__(16) float  g_X2   [(size_t)MROWS * Dm];     // pre-LN2 (fp32)

// ---------------------------------------------------------------------------
// Helpers
// ---------------------------------------------------------------------------
__device__ __forceinline__ void cp16(uint32_t dst_s, const void* src) {
    asm volatile("cp.async.cg.shared.global [%0], [%1], 16;\n" :: "r"(dst_s), "l"(src));
}
__device__ __forceinline__ void cp_commit() { asm volatile("cp.async.commit_group;\n"); }
__device__ __forceinline__ void cp_wait0()  { asm volatile("cp.async.wait_group 0;\n"); }

__device__ __forceinline__ void ldsm_x4(uint32_t& r0, uint32_t& r1, uint32_t& r2, uint32_t& r3,
                                        uint32_t addr) {
    asm volatile("ldmatrix.sync.aligned.m8n8.x4.shared.b16 {%0,%1,%2,%3},[%4];\n"
                 : "=r"(r0), "=r"(r1), "=r"(r2), "=r"(r3) : "r"(addr));
}
__device__ __forceinline__ void ldsm_x4t(uint32_t& r0, uint32_t& r1, uint32_t& r2, uint32_t& r3,
                                         uint32_t addr) {
    asm volatile("ldmatrix.sync.aligned.m8n8.x4.trans.shared.b16 {%0,%1,%2,%3},[%4];\n"
                 : "=r"(r0), "=r"(r1), "=r"(r2), "=r"(r3) : "r"(addr));
}
__device__ __forceinline__ void mma16(float* c, const uint32_t* a, const uint32_t* b) {
    asm volatile(
        "mma.sync.aligned.m16n8k16.row.col.f32.f16.f16.f32 "
        "{%0,%1,%2,%3},{%4,%5,%6,%7},{%8,%9},{%0,%1,%2,%3};\n"
        : "+f"(c[0]), "+f"(c[1]), "+f"(c[2]), "+f"(c[3])
        : "r"(a[0]), "r"(a[1]), "r"(a[2]), "r"(a[3]), "r"(b[0]), "r"(b[1]));
}

__device__ __forceinline__ float sigmoidf_(float v) { return 1.0f / (1.0f + expf(-v)); }
__device__ __forceinline__ float gelu_(float v) {
    return 0.5f * v * (1.0f + erff(v * 0.70710678118654752440f));
}

// ---------------------------------------------------------------------------
// fp32 -> fp16 conversion (8 elems/thread, vectorized)
// ---------------------------------------------------------------------------
__global__ void f2h(const float* __restrict__ in, __half* __restrict__ out, int n8) {
    int i = blockIdx.x * blockDim.x + threadIdx.x;
    if (i >= n8) return;
    const float4* src = (const float4*)in + i * 2;
    float4 a = src[0], b = src[1];
    __half2 h[4];
    h[0] = __floats2half2_rn(a.x, a.y);
    h[1] = __floats2half2_rn(a.z, a.w);
    h[2] = __floats2half2_rn(b.x, b.y);
    h[3] = __floats2half2_rn(b.z, b.w);
    ((uint4*)out)[i] = *(uint4*)h;
}

// ---------------------------------------------------------------------------
// fp16 GEMM: C[M,N] = A[M,K] @ W[K,N], fused epilogues.
//   EPI=0: SRU proj -> g_Zh | g_Fh=sig(+b_f) | g_Rh=sig(+b_r)   (A = g_Xh)
//   EPI=1: MLP up   -> g_H4h = gelu(v + b1)                     (A = g_X1h)
//   EPI=2: MLP down -> g_X2  = v + b2 + x1 (residual, fp32)     (A = g_H4h)
// Tile 128x128x32, 256 threads (2x4 warps @ 64x32), double-buffered cp.async,
// XOR-swizzled smem, ldmatrix fragment loads.
// ---------------------------------------------------------------------------
constexpr int BM = 128, BN = 128, BK = 32;

// A smem: 128 rows x 32 fp16 (64B/row, 4x16B chunks). phys = r*64 + (c ^ ((r>>1)&3))*16
__device__ __forceinline__ uint32_t aoff(int r, int c) {
    return (uint32_t)(r * 64 + ((c ^ ((r >> 1) & 3)) << 4));
}
// B smem: 32 rows x 128 fp16 (256B/row, 16x16B chunks). phys = k*256 + (c ^ (k&7))*16
__device__ __forceinline__ uint32_t boff(int k, int c) {
    return (uint32_t)(k * 256 + ((c ^ (k & 7)) << 4));
}

template<int EPI, int N, int K>
__global__ __launch_bounds__(256, 2) void gemm_h(
    const float* __restrict__ bias,
    const float* __restrict__ bias2)
{
    const __half* __restrict__ A =
        (EPI == 0) ? g_Xh : ((EPI == 1) ? g_X1h : g_H4h);
    const __half* __restrict__ W =
        (EPI == 0) ? g_Wsruh : ((EPI == 1) ? g_W1h : g_W2h);

    __shared__ __align__(128) __half As[2][BM * BK];   // 8KB each
    __shared__ __align__(128) __half Bs[2][BK * BN];   // 8KB each

    const int t    = threadIdx.x;
    const int m0   = blockIdx.y * BM;
    const int n0   = blockIdx.x * BN;
    const int lane = t & 31, wid = t >> 5;
    const int gq   = lane >> 2, tg = lane & 3;
    const int wm   = (wid >> 2) * 64;   // warp m offset
    const int wn   = (wid & 3) * 32;    // warp n offset

    const uint32_t sA = (uint32_t)__cvta_generic_to_shared(&As[0][0]);
    const uint32_t sB = (uint32_t)__cvta_generic_to_shared(&Bs[0][0]);
    const uint32_t bufA = (uint32_t)(BM * BK * 2);   // bytes per A buffer
    const uint32_t bufB = (uint32_t)(BK * BN * 2);

    float acc[4][4][4];
    #pragma unroll
    for (int i = 0; i < 4; i++)
        #pragma unroll
        for (int j = 0; j < 4; j++)
            #pragma unroll
            for (int r = 0; r < 4; r++) acc[i][j][r] = 0.0f;

    auto load_tiles = [&](int kt, int s) {
        #pragma unroll
        for (int i = 0; i < 2; i++) {              // A: 128x32 fp16 = 512 x 16B
            int idx = t + i * 256;
            int row = idx >> 2, c = idx & 3;
            cp16(sA + s * bufA + aoff(row, c),
                 A + (size_t)(m0 + row) * K + (size_t)kt * BK + c * 8);
        }
        #pragma unroll
        for (int i = 0; i < 2; i++) {              // B: 32x128 fp16 = 512 x 16B
            int idx = t + i * 256;
            int row = idx >> 4, c = idx & 15;
            cp16(sB + s * bufB + boff(row, c),
                 W + (size_t)((size_t)kt * BK + row) * N + n0 + c * 8);
        }
        cp_commit();
    };

    load_tiles(0, 0);
    const int KT = K / BK;

    // per-lane ldmatrix address components
    const int ltile = lane >> 3;       // 0..3 (matrix index group)
    const int lrow  = lane & 7;

    for (int kt = 0; kt < KT; ++kt) {
        cp_wait0();
        __syncthreads();
        if (kt + 1 < KT) load_tiles(kt + 1, (kt + 1) & 1);

        const uint32_t aBase = sA + (kt & 1) * bufA;
        const uint32_t bBase = sB + (kt & 1) * bufB;

        #pragma unroll
        for (int ks = 0; ks < 2; ++ks) {           // two k16 steps in BK=32
            uint32_t af[4][4], bf[4][2];
            // A fragments: ldmatrix.x4 per mi (m16 x k16)
            #pragma unroll
            for (int mi = 0; mi < 4; mi++) {
                int row = wm + mi * 16 + ((ltile & 1) << 3) + lrow;
                int c   = ks * 2 + (ltile >> 1);
                ldsm_x4(af[mi][0], af[mi][1], af[mi][2], af[mi][3],
                        aBase + aoff(row, c));
            }
            // B fragments: ldmatrix.x4.trans per ni-pair (k16 x n16)
            #pragma unroll
            for (int ni2 = 0; ni2 < 2; ni2++) {
                int k = ks * 16 + ((ltile & 1) << 3) + lrow;
                int c = (wn >> 3) + ni2 * 2 + (ltile >> 1);
                uint32_t r0, r1, r2, r3;
                ldsm_x4t(r0, r1, r2, r3, bBase + boff(k, c));
                bf[ni2 * 2 + 0][0] = r0; bf[ni2 * 2 + 0][1] = r1;
                bf[ni2 * 2 + 1][0] = r2; bf[ni2 * 2 + 1][1] = r3;
            }
            #pragma unroll
            for (int mi = 0; mi < 4; mi++)
                #pragma unroll
                for (int ni = 0; ni < 4; ni++)
                    mma16(acc[mi][ni], af[mi], bf[ni]);
        }
    }

    // Epilogue (acc layout: c0,c1 @ row gq col 2tg; c2,c3 @ row gq+8)
    #pragma unroll
    for (int mi = 0; mi < 4; mi++) {
        #pragma unroll
        for (int ni = 0; ni < 4; ni++) {
            #pragma unroll
            for (int half = 0; half < 2; half++) {
                int row = m0 + wm + mi * 16 + gq + half * 8;
                int col = n0 + wn + ni * 8 + tg * 2;
                float v0 = acc[mi][ni][half * 2 + 0];
                float v1 = acc[mi][ni][half * 2 + 1];
                size_t rw = (size_t)row;
                if (EPI == 0) {
                    if (col < Hh) {
                        *(__half2*)(g_Zh + rw * Hh + col) = __floats2half2_rn(v0, v1);
                    } else if (col < 2 * Hh) {
                        int h = col - Hh;
                        *(__half2*)(g_Fh + rw * Hh + h) = __floats2half2_rn(
                            sigmoidf_(v0 + bias[h]), sigmoidf_(v1 + bias[h + 1]));
                    } else {
                        int h = col - 2 * Hh;
                        *(__half2*)(g_Rh + rw * Hh + h) = __floats2half2_rn(
                            sigmoidf_(v0 + bias2[h]), sigmoidf_(v1 + bias2[h + 1]));
                    }
                } else if (EPI == 1) {
                    *(__half2*)(g_H4h + rw * N + col) = __floats2half2_rn(
                        gelu_(v0 + bias[col]), gelu_(v1 + bias[col + 1]));
                } else {
                    __half2 x1 = *(const __half2*)(g_X1h + rw * N + col);
                    float2 o;
                    o.x = v0 + bias[col]     + __half2float(__low2half(x1));
                    o.y = v1 + bias[col + 1] + __half2float(__high2half(x1));
                    *(float2*)(g_X2 + rw * N + col) = o;
                }
            }
        }
    }
}

// ---------------------------------------------------------------------------
// SRU recurrence + highway.  One thread per (b,h) chain (coalesced over h).
//   c_t = f*c + (1-f)*z ;  out = x + r*c + (1-r)*x = 2x + r*(c - x)
// ---------------------------------------------------------------------------
__global__ void sru_scan(const float* __restrict__ x)
{
    int t = blockIdx.x * blockDim.x + threadIdx.x;   // 0..8191
    int b = t >> 9;
    int h = t & (Hh - 1);
    size_t base = (size_t)b * Lseq * Hh + h;

    float c = 0.0f;
    #pragma unroll 8
    for (int l = 0; l < Lseq; ++l) {
        size_t i = base + (size_t)l * Hh;
        float f  = __half2float(g_Fh[i]);
        float z  = __half2float(g_Zh[i]);
        float r  = __half2float(g_Rh[i]);
        float xv = x[i];
        c = fmaf(f, c - z, z);
        g_HW[i] = fmaf(r, c - xv, 2.0f * xv);
    }
}

// ---------------------------------------------------------------------------
// LayerNorm over 512: 1 block/row, 128 threads x float4.
//   WHICH=0: g_HW(f32) -> g_X1h(f16) ;  WHICH=1: g_X2(f32) -> outp(f32)
// ---------------------------------------------------------------------------
template<int WHICH>
__global__ void ln512(const float* __restrict__ gamma,
                      const float* __restrict__ beta,
                      float* __restrict__ outp)
{
    const float* in = (WHICH == 0) ? (const float*)g_HW : (const float*)g_X2;

    size_t row = blockIdx.x;
    int t = threadIdx.x;

    float4 v = ((const float4*)(in + row * Dm))[t];
    float s  = v.x + v.y + v.z + v.w;
    float sq = v.x*v.x + v.y*v.y + v.z*v.z + v.w*v.w;

    #pragma unroll
    for (int o = 16; o > 0; o >>= 1) {
        s  += __shfl_xor_sync(0xffffffffu, s,  o);
        sq += __shfl_xor_sync(0xffffffffu, sq, o);
    }
    __shared__ float ssum[4], ssq[4];
    int w = t >> 5;
    if ((t & 31) == 0) { ssum[w] = s; ssq[w] = sq; }
    __syncthreads();
    float S  = ssum[0] + ssum[1] + ssum[2] + ssum[3];
    float SQ = ssq[0] + ssq[1] + ssq[2] + ssq[3];

    float mean = S * (1.0f / 512.0f);
    float var  = SQ * (1.0f / 512.0f) - mean * mean;
    float rstd = rsqrtf(var + 1e-5f);

    float4 gg = ((const float4*)gamma)[t];
    float4 bb = ((const float4*)beta)[t];
    float4 o4;
    o4.x = (v.x - mean) * rstd * gg.x + bb.x;
    o4.y = (v.y - mean) * rstd * gg.y + bb.y;
    o4.z = (v.z - mean) * rstd * gg.z + bb.z;
    o4.w = (v.w - mean) * rstd * gg.w + bb.w;

    if (WHICH == 0) {
        __half2 h0 = __floats2half2_rn(o4.x, o4.y);
        __half2 h1 = __floats2half2_rn(o4.z, o4.w);
        uint2 pk = { *(uint32_t*)&h0, *(uint32_t*)&h1 };
        ((uint2*)(g_X1h + row * Dm))[t] = pk;
    } else {
        ((float4*)(outp + row * Dm))[t] = o4;
    }
}

// ---------------------------------------------------------------------------
// Launch
// ---------------------------------------------------------------------------
extern "C" void kernel_launch(void* const* d_in, const int* in_sizes, int n_in,
                              void* d_out, int out_size)
{
    const float* x    = (const float*)d_in[0];
    const float* Wsru = (const float*)d_in[1];
    const float* b_f  = (const float*)d_in[2];
    const float* b_r  = (const float*)d_in[3];
    const float* ln1g = (const float*)d_in[4];
    const float* ln1b = (const float*)d_in[5];
    const float* W1   = (const float*)d_in[6];
    const float* b1   = (const float*)d_in[7];
    const float* W2   = (const float*)d_in[8];
    const float* b2   = (const float*)d_in[9];
    const float* ln2g = (const float*)d_in[10];
    const float* ln2b = (const float*)d_in[11];
    float* out = (float*)d_out;

    __half* dXh; __half* dWsru; __half* dW1; __half* dW2;
    cudaGetSymbolAddress((void**)&dXh,   g_Xh);
    cudaGetSymbolAddress((void**)&dWsru, g_Wsruh);
    cudaGetSymbolAddress((void**)&dW1,   g_W1h);
    cudaGetSymbolAddress((void**)&dW2,   g_W2h);

    // 0) fp32 -> fp16 pre-pass (x + all weights)
    {
        int n8 = (MROWS * Dm) / 8;
        f2h<<<(n8 + 255) / 256, 256>>>(x, dXh, n8);
        n8 = (Dm * 3 * Hh) / 8;
        f2h<<<(n8 + 255) / 256, 256>>>(Wsru, dWsru, n8);
        n8 = (Dm * DFF) / 8;
        f2h<<<(n8 + 255) / 256, 256>>>(W1, dW1, n8);
        n8 = (DFF * Dm) / 8;
        f2h<<<(n8 + 255) / 256, 256>>>(W2, dW2, n8);
    }

    // 1) u = x @ W_sru, fused gate sigmoids -> g_Zh, g_Fh, g_Rh
    gemm_h<0, 3 * Hh, Dm><<<dim3((3 * Hh) / BN, MROWS / BM), 256>>>(b_f, b_r);
    // 2) sequential recurrence + highway -> g_HW
    sru_scan<<<(Bb * Hh) / 64, 64>>>(x);
    // 3) LN1 -> g_X1h
    ln512<0><<<MROWS, 128>>>(ln1g, ln1b, nullptr);
    // 4) h = gelu(x1 @ W1 + b1) -> g_H4h
    gemm_h<1, DFF, Dm><<<dim3(DFF / BN, MROWS / BM), 256>>>(b1, nullptr);
    // 5) x2 = x1 + h @ W2 + b2 -> g_X2
    gemm_h<2, Dm, DFF><<<dim3(Dm / BN, MROWS / BM), 256>>>(b2, nullptr);
    // 6) LN2 -> d_out
    ln512<1><<<MROWS, 128>>>(ln2g, ln2b, out);
}

// round 4
// speedup vs baseline: 3.3286x; 2.2473x over previous
#include <cuda_runtime.h>
#include <cuda_fp16.h>
#include <cstdint>
#include <cstddef>

// ---------------------------------------------------------------------------
// Problem constants: B=16, L=4096, D=H=512
// ---------------------------------------------------------------------------
constexpr int Bb   = 16;
constexpr int Lseq = 4096;
constexpr int Dm   = 512;
constexpr int Hh   = 512;
constexpr int MROWS = Bb * Lseq;          // 65536
constexpr int DFF  = 2048;                // 4*D
constexpr int NSEG = 8;
constexpr int SEGL = Lseq / NSEG;         // 512
constexpr int NCH  = Bb * Hh;             // 8192 scan chains

// ---------------------------------------------------------------------------
// Scratch (device globals)
// ---------------------------------------------------------------------------
__device__ __align__(16) __half g_Xh   [(size_t)MROWS * Dm];     // x fp16 (GEMM1 A)
__device__ __align__(16) __half g_Wsruh[(size_t)Dm * 3 * Hh];    // [K,N] fp16
__device__ __align__(16) __half g_W1h  [(size_t)Dm * DFF];
__device__ __align__(16) __half g_W2h  [(size_t)DFF * Dm];
__device__ __align__(16) __half g_Zh   [(size_t)MROWS * Hh];
__device__ __align__(16) __half g_Fh   [(size_t)MROWS * Hh];
__device__ __align__(16) __half g_Rh   [(size_t)MROWS * Hh];
__device__ __align__(16) float  g_HW   [(size_t)MROWS * Dm];     // pre-LN1 (fp32)
__device__ __align__(16) __half g_X1h  [(size_t)MROWS * Dm];     // post-LN1
__device__ __align__(16) __half g_H4h  [(size_t)MROWS * DFF];    // gelu out
__device__ __align__(16) float  g_X2   [(size_t)MROWS * Dm];     // pre-LN2 (fp32)
__device__ float g_cend [NCH * NSEG];
__device__ float g_pend [NCH * NSEG];
__device__ float g_carry[NCH * NSEG];

// ---------------------------------------------------------------------------
// Helpers
// ---------------------------------------------------------------------------
__device__ __forceinline__ void cp16(uint32_t dst_s, const void* src) {
    asm volatile("cp.async.cg.shared.global [%0], [%1], 16;\n" :: "r"(dst_s), "l"(src));
}
__device__ __forceinline__ void cp_commit() { asm volatile("cp.async.commit_group;\n"); }
template<int NN>
__device__ __forceinline__ void cp_wait() { asm volatile("cp.async.wait_group %0;\n" :: "n"(NN)); }

__device__ __forceinline__ void ldsm_x4(uint32_t& r0, uint32_t& r1, uint32_t& r2, uint32_t& r3,
                                        uint32_t addr) {
    asm volatile("ldmatrix.sync.aligned.m8n8.x4.shared.b16 {%0,%1,%2,%3},[%4];\n"
                 : "=r"(r0), "=r"(r1), "=r"(r2), "=r"(r3) : "r"(addr));
}
__device__ __forceinline__ void ldsm_x4t(uint32_t& r0, uint32_t& r1, uint32_t& r2, uint32_t& r3,
                                         uint32_t addr) {
    asm volatile("ldmatrix.sync.aligned.m8n8.x4.trans.shared.b16 {%0,%1,%2,%3},[%4];\n"
                 : "=r"(r0), "=r"(r1), "=r"(r2), "=r"(r3) : "r"(addr));
}
__device__ __forceinline__ void mma16(float* c, const uint32_t* a, const uint32_t* b) {
    asm volatile(
        "mma.sync.aligned.m16n8k16.row.col.f32.f16.f16.f32 "
        "{%0,%1,%2,%3},{%4,%5,%6,%7},{%8,%9},{%0,%1,%2,%3};\n"
        : "+f"(c[0]), "+f"(c[1]), "+f"(c[2]), "+f"(c[3])
        : "r"(a[0]), "r"(a[1]), "r"(a[2]), "r"(a[3]), "r"(b[0]), "r"(b[1]));
}

__device__ __forceinline__ float sigmoidf_(float v) { return 1.0f / (1.0f + expf(-v)); }
__device__ __forceinline__ float gelu_(float v) {
    return 0.5f * v * (1.0f + erff(v * 0.70710678118654752440f));
}

// ---------------------------------------------------------------------------
// fp32 -> fp16 (8 elems/thread)
// ---------------------------------------------------------------------------
__global__ void f2h(const float* __restrict__ in, __half* __restrict__ out, int n8) {
    int i = blockIdx.x * blockDim.x + threadIdx.x;
    if (i >= n8) return;
    const float4* src = (const float4*)in + i * 2;
    float4 a = src[0], b = src[1];
    __half2 h[4];
    h[0] = __floats2half2_rn(a.x, a.y);
    h[1] = __floats2half2_rn(a.z, a.w);
    h[2] = __floats2half2_rn(b.x, b.y);
    h[3] = __floats2half2_rn(b.z, b.w);
    ((uint4*)out)[i] = *(uint4*)h;
}

// ---------------------------------------------------------------------------
// fp16 GEMM: C[M,N] = A[M,K] @ W[K,N], fused epilogues.
// Tile 128x128x64, 3-stage cp.async pipeline, 256 threads (2x4 warps @ 64x32),
// XOR-swizzled smem, ldmatrix fragment loads (proven R2 scheme, BK doubled).
//   EPI=0: SRU proj -> g_Zh | g_Fh=sig(+b_f) | g_Rh=sig(+b_r)   (A = g_Xh)
//   EPI=1: MLP up   -> g_H4h = gelu(v + b1)                     (A = g_X1h)
//   EPI=2: MLP down -> g_X2  = v + b2 + x1 (fp32)               (A = g_H4h)
// ---------------------------------------------------------------------------
constexpr int BM = 128, BN = 128, BK = 64;
constexpr int STG_BYTES = BM * BK * 2 + BK * BN * 2;   // 16KB + 16KB = 32KB
constexpr int GSMEM = 3 * STG_BYTES;                    // 96KB dynamic

// A smem: 128 rows x 64 fp16 (128B/row, 8x16B chunks). phys = r*128 + ((c ^ (r&7))<<4)
__device__ __forceinline__ uint32_t aoff(int r, int c) {
    return (uint32_t)(r * 128 + ((c ^ (r & 7)) << 4));
}
// B smem: 64 rows x 128 fp16 (256B/row, 16x16B chunks). phys = k*256 + ((c ^ (k&7))<<4)
__device__ __forceinline__ uint32_t boff(int k, int c) {
    return (uint32_t)(k * 256 + ((c ^ (k & 7)) << 4));
}

template<int EPI, int N, int K>
__global__ __launch_bounds__(256, 2) void gemm_h(
    const float* __restrict__ bias,
    const float* __restrict__ bias2)
{
    extern __shared__ __align__(1024) char dsm[];

    const __half* __restrict__ A =
        (EPI == 0) ? g_Xh : ((EPI == 1) ? g_X1h : g_H4h);
    const __half* __restrict__ W =
        (EPI == 0) ? g_Wsruh : ((EPI == 1) ? g_W1h : g_W2h);

    const int t    = threadIdx.x;
    const int m0   = blockIdx.y * BM;
    const int n0   = blockIdx.x * BN;
    const int lane = t & 31, wid = t >> 5;
    const int gq   = lane >> 2, tg = lane & 3;
    const int wm   = (wid >> 2) * 64;   // warp m offset
    const int wn   = (wid & 3) * 32;    // warp n offset

    const uint32_t sBase = (uint32_t)__cvta_generic_to_shared(dsm);

    float acc[4][4][4];
    #pragma unroll
    for (int i = 0; i < 4; i++)
        #pragma unroll
        for (int j = 0; j < 4; j++)
            #pragma unroll
            for (int r = 0; r < 4; r++) acc[i][j][r] = 0.0f;

    auto loadChunk = [&](int kt, int s) {
        const uint32_t aB = sBase + (uint32_t)s * STG_BYTES;
        const uint32_t bB = aB + BM * BK * 2;
        #pragma unroll
        for (int i = 0; i < 4; i++) {              // A: 128x64 fp16 = 1024 x 16B
            int idx = t + i * 256;
            int row = idx >> 3, c = idx & 7;
            cp16(aB + aoff(row, c),
                 A + (size_t)(m0 + row) * K + (size_t)kt * BK + c * 8);
        }
        #pragma unroll
        for (int i = 0; i < 4; i++) {              // B: 64x128 fp16 = 1024 x 16B
            int idx = t + i * 256;
            int row = idx >> 4, c = idx & 15;
            cp16(bB + boff(row, c),
                 W + (size_t)((size_t)kt * BK + row) * N + n0 + c * 8);
        }
        cp_commit();
    };

    const int KT = K / BK;
    loadChunk(0, 0);
    if (KT > 1) loadChunk(1, 1);

    const int ltile = lane >> 3;       // 0..3
    const int lrow  = lane & 7;

    for (int kt = 0; kt < KT; ++kt) {
        if (kt + 2 <= KT) cp_wait<1>(); else cp_wait<0>();
        __syncthreads();
        if (kt + 2 < KT) loadChunk(kt + 2, (kt + 2) % 3);

        const uint32_t aBase = sBase + (uint32_t)((kt % 3) * STG_BYTES);
        const uint32_t bBase = aBase + BM * BK * 2;

        #pragma unroll
        for (int ks = 0; ks < 4; ++ks) {           // four k16 steps in BK=64
            uint32_t af[4][4], bf[4][2];
            #pragma unroll
            for (int mi = 0; mi < 4; mi++) {
                int row = wm + mi * 16 + ((ltile & 1) << 3) + lrow;
                int c   = ks * 2 + (ltile >> 1);
                ldsm_x4(af[mi][0], af[mi][1], af[mi][2], af[mi][3],
                        aBase + aoff(row, c));
            }
            #pragma unroll
            for (int ni2 = 0; ni2 < 2; ni2++) {
                int k = ks * 16 + ((ltile & 1) << 3) + lrow;
                int c = (wn >> 3) + ni2 * 2 + (ltile >> 1);
                uint32_t r0, r1, r2, r3;
                ldsm_x4t(r0, r1, r2, r3, bBase + boff(k, c));
                bf[ni2 * 2 + 0][0] = r0; bf[ni2 * 2 + 0][1] = r1;
                bf[ni2 * 2 + 1][0] = r2; bf[ni2 * 2 + 1][1] = r3;
            }
            #pragma unroll
            for (int mi = 0; mi < 4; mi++)
                #pragma unroll
                for (int ni = 0; ni < 4; ni++)
                    mma16(acc[mi][ni], af[mi], bf[ni]);
        }
    }

    // Epilogue (R2-proven): acc c0,c1 @ row gq col 2tg; c2,c3 @ row gq+8
    #pragma unroll
    for (int mi = 0; mi < 4; mi++) {
        #pragma unroll
        for (int ni = 0; ni < 4; ni++) {
            #pragma unroll
            for (int half = 0; half < 2; half++) {
                int row = m0 + wm + mi * 16 + gq + half * 8;
                int col = n0 + wn + ni * 8 + tg * 2;
                float v0 = acc[mi][ni][half * 2 + 0];
                float v1 = acc[mi][ni][half * 2 + 1];
                size_t rw = (size_t)row;
                if (EPI == 0) {
                    if (col < Hh) {
                        *(__half2*)(g_Zh + rw * Hh + col) = __floats2half2_rn(v0, v1);
                    } else if (col < 2 * Hh) {
                        int h = col - Hh;
                        *(__half2*)(g_Fh + rw * Hh + h) = __floats2half2_rn(
                            sigmoidf_(v0 + bias[h]), sigmoidf_(v1 + bias[h + 1]));
                    } else {
                        int h = col - 2 * Hh;
                        *(__half2*)(g_Rh + rw * Hh + h) = __floats2half2_rn(
                            sigmoidf_(v0 + bias2[h]), sigmoidf_(v1 + bias2[h + 1]));
                    }
                } else if (EPI == 1) {
                    *(__half2*)(g_H4h + rw * N + col) = __floats2half2_rn(
                        gelu_(v0 + bias[col]), gelu_(v1 + bias[col + 1]));
                } else {
                    __half2 x1 = *(const __half2*)(g_X1h + rw * N + col);
                    float2 o;
                    o.x = v0 + bias[col]     + __half2float(__low2half(x1));
                    o.y = v1 + bias[col + 1] + __half2float(__high2half(x1));
                    *(float2*)(g_X2 + rw * N + col) = o;
                }
            }
        }
    }
}

// ---------------------------------------------------------------------------
// Segmented SRU scan (exact).  Chain (b,h) split into NSEG=8 segments of 512.
//  A: per-(b,h,seg) local scan with c0=0 -> (c_end, prod_f)
//  B: sequential carry chain over segments (8192 threads x 8 steps)
//  C: re-run recurrence with correct carry-in; write highway output to g_HW
// ---------------------------------------------------------------------------
__global__ void scanA()
{
    int t = blockIdx.x * blockDim.x + threadIdx.x;   // 0..65535
    int q = t & (NCH - 1);
    int s = t >> 13;
    int b = q >> 9;
    int h = q & (Hh - 1);
    size_t base = ((size_t)b * Lseq + (size_t)s * SEGL) * Hh + h;

    float c = 0.0f, p = 1.0f;
    #pragma unroll 8
    for (int l = 0; l < SEGL; ++l) {
        size_t i = base + (size_t)l * Hh;
        float f = __half2float(g_Fh[i]);
        float z = __half2float(g_Zh[i]);
        c = fmaf(f, c - z, z);
        p *= f;
    }
    g_cend[t] = c;
    g_pend[t] = p;
}

__global__ void scanB()
{
    int q = blockIdx.x * blockDim.x + threadIdx.x;   // 0..8191
    float carry = 0.0f;
    #pragma unroll
    for (int s = 0; s < NSEG; ++s) {
        int idx = s * NCH + q;
        g_carry[idx] = carry;
        carry = g_cend[idx] + g_pend[idx] * carry;
    }
}

__global__ void scanC(const float* __restrict__ x)
{
    int t = blockIdx.x * blockDim.x + threadIdx.x;   // 0..65535
    int q = t & (NCH - 1);
    int s = t >> 13;
    int b = q >> 9;
    int h = q & (Hh - 1);
    size_t base = ((size_t)b * Lseq + (size_t)s * SEGL) * Hh + h;

    float c = g_carry[s * NCH + q];
    #pragma unroll 8
    for (int l = 0; l < SEGL; ++l) {
        size_t i = base + (size_t)l * Hh;
        float f  = __half2float(g_Fh[i]);
        float z  = __half2float(g_Zh[i]);
        float r  = __half2float(g_Rh[i]);
        float xv = x[i];
        c = fmaf(f, c - z, z);
        g_HW[i] = fmaf(r, c - xv, 2.0f * xv);
    }
}

// ---------------------------------------------------------------------------
// LayerNorm over 512: 1 block/row, 128 threads x float4.
//   WHICH=0: g_HW(f32) -> g_X1h(f16) ;  WHICH=1: g_X2(f32) -> outp(f32)
// ---------------------------------------------------------------------------
template<int WHICH>
__global__ void ln512(const float* __restrict__ gamma,
                      const float* __restrict__ beta,
                      float* __restrict__ outp)
{
    const float* in = (WHICH == 0) ? (const float*)g_HW : (const float*)g_X2;

    size_t row = blockIdx.x;
    int t = threadIdx.x;

    float4 v = ((const float4*)(in + row * Dm))[t];
    float s  = v.x + v.y + v.z + v.w;
    float sq = v.x*v.x + v.y*v.y + v.z*v.z + v.w*v.w;

    #pragma unroll
    for (int o = 16; o > 0; o >>= 1) {
        s  += __shfl_xor_sync(0xffffffffu, s,  o);
        sq += __shfl_xor_sync(0xffffffffu, sq, o);
    }
    __shared__ float ssum[4], ssq[4];
    int w = t >> 5;
    if ((t & 31) == 0) { ssum[w] = s; ssq[w] = sq; }
    __syncthreads();
    float S  = ssum[0] + ssum[1] + ssum[2] + ssum[3];
    float SQ = ssq[0] + ssq[1] + ssq[2] + ssq[3];

    float mean = S * (1.0f / 512.0f);
    float var  = SQ * (1.0f / 512.0f) - mean * mean;
    float rstd = rsqrtf(var + 1e-5f);

    float4 gg = ((const float4*)gamma)[t];
    float4 bb = ((const float4*)beta)[t];
    float4 o4;
    o4.x = (v.x - mean) * rstd * gg.x + bb.x;
    o4.y = (v.y - mean) * rstd * gg.y + bb.y;
    o4.z = (v.z - mean) * rstd * gg.z + bb.z;
    o4.w = (v.w - mean) * rstd * gg.w + bb.w;

    if (WHICH == 0) {
        __half2 h0 = __floats2half2_rn(o4.x, o4.y);
        __half2 h1 = __floats2half2_rn(o4.z, o4.w);
        uint2 pk = { *(uint32_t*)&h0, *(uint32_t*)&h1 };
        ((uint2*)(g_X1h + row * Dm))[t] = pk;
    } else {
        ((float4*)(outp + row * Dm))[t] = o4;
    }
}

// ---------------------------------------------------------------------------
// Launch
// ---------------------------------------------------------------------------
extern "C" void kernel_launch(void* const* d_in, const int* in_sizes, int n_in,
                              void* d_out, int out_size)
{
    const float* x    = (const float*)d_in[0];
    const float* Wsru = (const float*)d_in[1];
    const float* b_f  = (const float*)d_in[2];
    const float* b_r  = (const float*)d_in[3];
    const float* ln1g = (const float*)d_in[4];
    const float* ln1b = (const float*)d_in[5];
    const float* W1   = (const float*)d_in[6];
    const float* b1   = (const float*)d_in[7];
    const float* W2   = (const float*)d_in[8];
    const float* b2   = (const float*)d_in[9];
    const float* ln2g = (const float*)d_in[10];
    const float* ln2b = (const float*)d_in[11];
    float* out = (float*)d_out;

    static bool attr_done = false;
    if (!attr_done) {
        cudaFuncSetAttribute(gemm_h<0, 3 * Hh, Dm>,
                             cudaFuncAttributeMaxDynamicSharedMemorySize, GSMEM);
        cudaFuncSetAttribute(gemm_h<1, DFF, Dm>,
                             cudaFuncAttributeMaxDynamicSharedMemorySize, GSMEM);
        cudaFuncSetAttribute(gemm_h<2, Dm, DFF>,
                             cudaFuncAttributeMaxDynamicSharedMemorySize, GSMEM);
        attr_done = true;
    }

    __half* dXh; __half* dWsru; __half* dW1; __half* dW2;
    cudaGetSymbolAddress((void**)&dXh,   g_Xh);
    cudaGetSymbolAddress((void**)&dWsru, g_Wsruh);
    cudaGetSymbolAddress((void**)&dW1,   g_W1h);
    cudaGetSymbolAddress((void**)&dW2,   g_W2h);

    // 0) fp32 -> fp16 pre-pass (x + all weights)
    {
        int n8 = (MROWS * Dm) / 8;
        f2h<<<(n8 + 255) / 256, 256>>>(x, dXh, n8);
        n8 = (Dm * 3 * Hh) / 8;
        f2h<<<(n8 + 255) / 256, 256>>>(Wsru, dWsru, n8);
        n8 = (Dm * DFF) / 8;
        f2h<<<(n8 + 255) / 256, 256>>>(W1, dW1, n8);
        n8 = (DFF * Dm) / 8;
        f2h<<<(n8 + 255) / 256, 256>>>(W2, dW2, n8);
    }

    // 1) u = x @ W_sru, fused gate sigmoids -> g_Zh/g_Fh/g_Rh
    gemm_h<0, 3 * Hh, Dm><<<dim3((3 * Hh) / BN, MROWS / BM), 256, GSMEM>>>(b_f, b_r);
    // 2) segmented recurrence + highway -> g_HW
    scanA<<<(NCH * NSEG) / 256, 256>>>();
    scanB<<<NCH / 256, 256>>>();
    scanC<<<(NCH * NSEG) / 256, 256>>>(x);
    // 3) LN1 -> g_X1h
    ln512<0><<<MROWS, 128>>>(ln1g, ln1b, nullptr);
    // 4) h = gelu(x1 @ W1 + b1) -> g_H4h
    gemm_h<1, DFF, Dm><<<dim3(DFF / BN, MROWS / BM), 256, GSMEM>>>(b1, nullptr);
    // 5) x2 = x1 + h @ W2 + b2 -> g_X2
    gemm_h<2, Dm, DFF><<<dim3(Dm / BN, MROWS / BM), 256, GSMEM>>>(b2, nullptr);
    // 6) LN2 -> d_out
    ln512<1><<<MROWS, 128>>>(ln2g, ln2b, out);
}